// round 14
// baseline (speedup 1.0000x reference)
#include <cuda_runtime.h>
#include <cuda_fp16.h>
#include <math.h>
#include <cstdint>

#define NB 4096
#define ND 128
#define TILE 128
#define NT 1024                 // 32 x 32 tiles
#define GRID_SIM 444            // 3 CTAs per SM, persistent
#define STRIDE 144              // smem bytes per 128-col fp8 row (128 + 16 pad)
#define SM_TILE (128 * STRIDE)  // 18432 B per tile
#define BUF_BYTES (2 * SM_TILE) // A + B = 36864 B
#define SM_TOTAL (2 * BUF_BYTES)// double buffered = 73728 B
// z scaled by sqrt(4*log2(e)) = 2.4022448 -> accumulator = sim * 4*log2(e),
// so exp(sim/T) = ex2(accumulator) directly.
#define NORM_SCALE 2.4022448f

// ---------------- scratch (no allocations allowed) ----------------
__device__ __align__(16) uint32_t g_zi_f8[NB * 32];  // e4m3 z_i*2.4022
__device__ __align__(16) uint32_t g_zj_f8[NB * 32];  // e4m3 z_j*2.4022
__device__ float g_rowsum[NB];
__device__ float g_colsum[NB];
__device__ float g_pos[NB];
__device__ int g_done;          // last-CTA completion counter

__device__ __forceinline__ uint32_t smem_u32(const void* p) {
    uint32_t a;
    asm("{ .reg .u64 t; cvta.to.shared.u64 t, %1; cvt.u32.u64 %0, t; }" : "=r"(a) : "l"(p));
    return a;
}
__device__ __forceinline__ void cp16(uint32_t dst, const void* src) {
    asm volatile("cp.async.cg.shared.global [%0], [%1], 16;" :: "r"(dst), "l"(src));
}
__device__ __forceinline__ void ldm_x4(uint32_t& r0, uint32_t& r1, uint32_t& r2,
                                       uint32_t& r3, uint32_t addr) {
    asm volatile("ldmatrix.sync.aligned.m8n8.x4.shared.b16 {%0,%1,%2,%3}, [%4];"
                 : "=r"(r0), "=r"(r1), "=r"(r2), "=r"(r3) : "r"(addr));
}
__device__ __forceinline__ void mma_fp8_h(uint32_t& c0, uint32_t& c1,
                                          uint32_t a0, uint32_t a1, uint32_t a2, uint32_t a3,
                                          uint32_t b0, uint32_t b1) {
    asm volatile("mma.sync.aligned.m16n8k32.row.col.f16.e4m3.e4m3.f16 "
                 "{%0,%1}, {%2,%3,%4,%5}, {%6,%7}, {%0,%1};"
                 : "+r"(c0), "+r"(c1)
                 : "r"(a0), "r"(a1), "r"(a2), "r"(a3), "r"(b0), "r"(b1));
}
__device__ __forceinline__ uint32_t ex2h2(uint32_t x) {
    uint32_t r;
    asm("ex2.approx.f16x2 %0, %1;" : "=r"(r) : "r"(x));
    return r;
}
__device__ __forceinline__ uint32_t haddu(uint32_t a, uint32_t b) {
    uint32_t r;
    asm("add.rn.f16x2 %0, %1, %2;" : "=r"(r) : "r"(a), "r"(b));
    return r;
}
__device__ __forceinline__ float2 h2f2(uint32_t h) {
    __half2 v = *(__half2*)&h;
    return __half22float2(v);
}
__device__ __forceinline__ uint32_t pack_e4m3(float x, float y, float z, float w) {
    uint16_t lo, hi;
    asm("cvt.rn.satfinite.e4m3x2.f32 %0, %1, %2;" : "=h"(lo) : "f"(y), "f"(x));
    asm("cvt.rn.satfinite.e4m3x2.f32 %0, %1, %2;" : "=h"(hi) : "f"(w), "f"(z));
    return (uint32_t)lo | ((uint32_t)hi << 16);
}

// ---------------------------------------------------------------------------
// Kernel 1: warp-per-row L2 normalize, write e4m3 z*2.4022, fp32 positives.
// PDL: signal launch completion at entry so sim's CTAs can spin up behind us.
// ---------------------------------------------------------------------------
__global__ void __launch_bounds__(256) norm_kernel(const float* __restrict__ emb_i,
                                                   const float* __restrict__ emb_j) {
    if (threadIdx.x == 0) cudaTriggerProgrammaticLaunchCompletion();
    int lane = threadIdx.x & 31;
    int row = blockIdx.x * 8 + (threadIdx.x >> 5);
    const float4 a = ((const float4*)emb_i)[row * 32 + lane];
    const float4 b = ((const float4*)emb_j)[row * 32 + lane];
    float ssi = a.x * a.x + a.y * a.y + a.z * a.z + a.w * a.w;
    float ssj = b.x * b.x + b.y * b.y + b.z * b.z + b.w * b.w;
    float dot = a.x * b.x + a.y * b.y + a.z * b.z + a.w * b.w;
#pragma unroll
    for (int o = 16; o > 0; o >>= 1) {
        ssi += __shfl_xor_sync(0xffffffffu, ssi, o);
        ssj += __shfl_xor_sync(0xffffffffu, ssj, o);
        dot += __shfl_xor_sync(0xffffffffu, dot, o);
    }
    float inv_i = 1.0f / fmaxf(sqrtf(ssi), 1e-12f);
    float inv_j = 1.0f / fmaxf(sqrtf(ssj), 1e-12f);
    float si = inv_i * NORM_SCALE;
    float sj = inv_j * NORM_SCALE;

    g_zi_f8[row * 32 + lane] = pack_e4m3(a.x * si, a.y * si, a.z * si, a.w * si);
    g_zj_f8[row * 32 + lane] = pack_e4m3(b.x * sj, b.y * sj, b.z * sj, b.w * sj);
    if (lane == 0) {
        g_pos[row]    = dot * inv_i * inv_j;   // exact fp32 positive
        g_rowsum[row] = 0.0f;
        g_colsum[row] = 0.0f;
    }
}

// ---------------------------------------------------------------------------
// Kernel 2: persistent fp8 MMA (f16 accum), single-sync pipeline, REDG
// epilogue, fused last-CTA final reduce. PDL-gated on norm completion.
// ---------------------------------------------------------------------------
__device__ __forceinline__ void prefetch_tile(int t, uint32_t dst, int tid) {
    int bx = t & 31, by = t >> 5;
    const char* srcA = (const char*)g_zi_f8 + (size_t)by * 128 * 128;
    const char* srcB = (const char*)g_zj_f8 + (size_t)bx * 128 * 128;
#pragma unroll
    for (int it = 0; it < 4; it++) {
        int i = it * 256 + tid;                 // [0,1024): row=i>>3, chunk=i&7
        uint32_t soff = (uint32_t)(i >> 3) * STRIDE + (uint32_t)(i & 7) * 16;
        cp16(dst + soff, srcA + (size_t)i * 16);
        cp16(dst + SM_TILE + soff, srcB + (size_t)i * 16);
    }
    asm volatile("cp.async.commit_group;" ::: "memory");
}

__global__ void __launch_bounds__(256, 3) sim_kernel(float* __restrict__ out) {
    extern __shared__ char smem[];
    uint32_t sbase = smem_u32(smem);
    int tid = threadIdx.x;
    int wid = tid >> 5;
    int l = tid & 31;
    int m_base = (wid & 1) * 64;
    int n_base = (wid >> 1) * 32;
    uint32_t lrow  = (uint32_t)(((l >> 3) & 1) * 8 + (l & 7));
    uint32_t lcolb = (uint32_t)((l >> 4) * 16);

    // PDL: wait for norm_kernel's writes to be visible.
    cudaGridDependencySynchronize();

    int t = blockIdx.x;
    if (t < NT) prefetch_tile(t, sbase, tid);     // prologue: buffer 0
    int buf = 0;

    for (; t < NT; t += GRID_SIM) {
        asm volatile("cp.async.wait_group 0;" ::: "memory");
        __syncthreads();      // cur tile resident; ALL warps done with buf^1 reads
        int tn = t + GRID_SIM;
        if (tn < NT)          // safe now: overlaps with compute below
            prefetch_tile(tn, sbase + (uint32_t)(buf ^ 1) * BUF_BYTES, tid);

        uint32_t cur = sbase + (uint32_t)buf * BUF_BYTES;
        uint32_t a_base = cur + (m_base + lrow) * STRIDE + lcolb;
        uint32_t b_base = cur + SM_TILE + (n_base + lrow) * STRIDE + lcolb;

        uint32_t c[4][4][2];                      // packed half2 accumulators
#pragma unroll
        for (int mf = 0; mf < 4; mf++)
#pragma unroll
            for (int nf = 0; nf < 4; nf++) { c[mf][nf][0] = 0u; c[mf][nf][1] = 0u; }

#pragma unroll
        for (int ks = 0; ks < 4; ks++) {          // K=128 fp8, 32 per MMA
            uint32_t koff = (uint32_t)ks * 32;
            uint32_t a0[4], a1[4], a2[4], a3[4];
#pragma unroll
            for (int mf = 0; mf < 4; mf++)
                ldm_x4(a0[mf], a1[mf], a2[mf], a3[mf],
                       a_base + (uint32_t)mf * 16 * STRIDE + koff);
            uint32_t bl0[2], bl1[2], bl2[2], bl3[2];
#pragma unroll
            for (int nh = 0; nh < 2; nh++)
                ldm_x4(bl0[nh], bl1[nh], bl2[nh], bl3[nh],
                       b_base + (uint32_t)nh * 16 * STRIDE + koff);
#pragma unroll
            for (int mf = 0; mf < 4; mf++) {
#pragma unroll
                for (int nh = 0; nh < 2; nh++) {
                    mma_fp8_h(c[mf][nh * 2][0], c[mf][nh * 2][1],
                              a0[mf], a1[mf], a2[mf], a3[mf], bl0[nh], bl2[nh]);
                    mma_fp8_h(c[mf][nh * 2 + 1][0], c[mf][nh * 2 + 1][1],
                              a0[mf], a1[mf], a2[mf], a3[mf], bl1[nh], bl3[nh]);
                }
            }
        }

        // --- epilogue: ex2.f16x2 + packed-half2 sums -> direct global REDG ---
        // c0 -> rows r @ (cc,cc+1); c1 -> rows r+8; r=l/4, cc=2(l%4)
        int rowBase = (t >> 5) * TILE;
        int colBase = (t & 31) * TILE;
        uint32_t hr0[4], hr1[4], cacc[4];
#pragma unroll
        for (int i = 0; i < 4; i++) { hr0[i] = 0u; hr1[i] = 0u; cacc[i] = 0u; }
#pragma unroll
        for (int mf = 0; mf < 4; mf++) {
#pragma unroll
            for (int nf = 0; nf < 4; nf++) {
                uint32_t e0 = ex2h2(c[mf][nf][0]);
                uint32_t e1 = ex2h2(c[mf][nf][1]);
                hr0[mf] = haddu(hr0[mf], e0);
                hr1[mf] = haddu(hr1[mf], e1);
                cacc[nf] = haddu(cacc[nf], haddu(e0, e1));
            }
        }
        // rows: packed shuffle over col-pair lanes (l&3), then REDG pair
#pragma unroll
        for (int mf = 0; mf < 4; mf++) {
            uint32_t a = hr0[mf], b = hr1[mf];
#pragma unroll
            for (int o = 1; o <= 2; o <<= 1) {
                a = haddu(a, __shfl_xor_sync(0xffffffffu, a, o));
                b = haddu(b, __shfl_xor_sync(0xffffffffu, b, o));
            }
            if ((l & 3) == 0) {
                float2 fa = h2f2(a), fb = h2f2(b);
                int r = rowBase + m_base + mf * 16 + (l >> 2);
                atomicAdd(&g_rowsum[r], fa.x + fa.y);
                atomicAdd(&g_rowsum[r + 8], fb.x + fb.y);
            }
        }
        // cols: packed shuffle over row lanes (l>>2), then REDG per component
#pragma unroll
        for (int nf = 0; nf < 4; nf++) {
            uint32_t a = cacc[nf];
#pragma unroll
            for (int o = 4; o <= 16; o <<= 1)
                a = haddu(a, __shfl_xor_sync(0xffffffffu, a, o));
            if (l < 4) {
                float2 fa = h2f2(a);
                int cc = colBase + n_base + nf * 8 + 2 * l;
                atomicAdd(&g_colsum[cc], fa.x);
                atomicAdd(&g_colsum[cc + 1], fa.y);
            }
        }
        buf ^= 1;
    }

    // ---------- fused final: last CTA to finish reduces the loss ----------
    __shared__ int s_rank;
    __shared__ double sd[256];
    __threadfence();          // make this CTA's REDGs globally visible
    __syncthreads();
    if (tid == 0) s_rank = atomicAdd(&g_done, 1);
    __syncthreads();
    if (s_rank == GRID_SIM - 1) {
        __threadfence();      // acquire: all other CTAs' sums visible
        double acc = 0.0;
        for (int i = tid; i < NB; i += 256) {
            acc += (double)__logf(g_rowsum[i]) + (double)__logf(g_colsum[i])
                 - 8.0 * (double)g_pos[i];        // 2/T = 8
        }
        sd[tid] = acc;
        __syncthreads();
#pragma unroll
        for (int o = 128; o > 0; o >>= 1) {
            if (tid < o) sd[tid] += sd[tid + o];
            __syncthreads();
        }
        if (tid == 0) {
            out[0] = (float)(sd[0] / (2.0 * NB));
            g_done = 0;       // reset for next graph replay
        }
    }
}

extern "C" void kernel_launch(void* const* d_in, const int* in_sizes, int n_in,
                              void* d_out, int out_size) {
    const float* emb_i = (const float*)d_in[0];
    const float* emb_j = (const float*)d_in[1];
    float* out = (float*)d_out;

    cudaFuncSetAttribute(sim_kernel, cudaFuncAttributeMaxDynamicSharedMemorySize, SM_TOTAL);

    norm_kernel<<<NB / 8, 256>>>(emb_i, emb_j);

    // Launch sim with Programmatic Dependent Launch: its CTAs spin up while
    // norm finishes, gated by cudaGridDependencySynchronize() in-kernel.
    cudaLaunchConfig_t cfg = {};
    cfg.gridDim = dim3(GRID_SIM, 1, 1);
    cfg.blockDim = dim3(256, 1, 1);
    cfg.dynamicSmemBytes = SM_TOTAL;
    cudaLaunchAttribute attrs[1];
    attrs[0].id = cudaLaunchAttributeProgrammaticStreamSerialization;
    attrs[0].val.programmaticStreamSerializationAllowed = 1;
    cfg.attrs = attrs;
    cfg.numAttrs = 1;
    cudaError_t err = cudaLaunchKernelEx(&cfg, sim_kernel, out);
    if (err != cudaSuccess) {
        // Fallback: plain launch (no PDL) if the attribute is rejected.
        sim_kernel<<<GRID_SIM, 256, SM_TOTAL>>>(out);
    }
}

// round 15
// speedup vs baseline: 1.1221x; 1.1221x over previous
#include <cuda_runtime.h>
#include <cuda_fp16.h>
#include <math.h>
#include <cstdint>

#define NB 4096
#define ND 128
#define TILE 128
#define NT 1024                 // 32 x 32 tiles
#define GRID_SIM 296            // 2 CTAs per SM, persistent (no spills)
#define STRIDE 144              // smem bytes per 128-col fp8 row (128 + 16 pad)
#define SM_TILE (128 * STRIDE)  // 18432 B per tile
#define BUF_BYTES (2 * SM_TILE) // A + B = 36864 B
#define SM_TOTAL (2 * BUF_BYTES)// double buffered = 73728 B
// z scaled by sqrt(4*log2(e)) = 2.4022448 -> accumulator = sim * 4*log2(e),
// so exp(sim/T) = ex2(accumulator) directly.
#define NORM_SCALE 2.4022448f

// ---------------- scratch (no allocations allowed) ----------------
__device__ __align__(16) uint32_t g_zi_f8[NB * 32];  // e4m3 z_i*2.4022
__device__ __align__(16) uint32_t g_zj_f8[NB * 32];  // e4m3 z_j*2.4022
__device__ float g_rowsum[NB];
__device__ float g_colsum[NB];
__device__ float g_pos[NB];

__device__ __forceinline__ uint32_t smem_u32(const void* p) {
    uint32_t a;
    asm("{ .reg .u64 t; cvta.to.shared.u64 t, %1; cvt.u32.u64 %0, t; }" : "=r"(a) : "l"(p));
    return a;
}
__device__ __forceinline__ void cp16(uint32_t dst, const void* src) {
    asm volatile("cp.async.cg.shared.global [%0], [%1], 16;" :: "r"(dst), "l"(src));
}
__device__ __forceinline__ void ldm_x4(uint32_t& r0, uint32_t& r1, uint32_t& r2,
                                       uint32_t& r3, uint32_t addr) {
    asm volatile("ldmatrix.sync.aligned.m8n8.x4.shared.b16 {%0,%1,%2,%3}, [%4];"
                 : "=r"(r0), "=r"(r1), "=r"(r2), "=r"(r3) : "r"(addr));
}
__device__ __forceinline__ void mma_fp8_h(uint32_t& c0, uint32_t& c1,
                                          uint32_t a0, uint32_t a1, uint32_t a2, uint32_t a3,
                                          uint32_t b0, uint32_t b1) {
    asm volatile("mma.sync.aligned.m16n8k32.row.col.f16.e4m3.e4m3.f16 "
                 "{%0,%1}, {%2,%3,%4,%5}, {%6,%7}, {%0,%1};"
                 : "+r"(c0), "+r"(c1)
                 : "r"(a0), "r"(a1), "r"(a2), "r"(a3), "r"(b0), "r"(b1));
}
__device__ __forceinline__ uint32_t ex2h2(uint32_t x) {
    uint32_t r;
    asm("ex2.approx.f16x2 %0, %1;" : "=r"(r) : "r"(x));
    return r;
}
__device__ __forceinline__ uint32_t haddu(uint32_t a, uint32_t b) {
    uint32_t r;
    asm("add.rn.f16x2 %0, %1, %2;" : "=r"(r) : "r"(a), "r"(b));
    return r;
}
__device__ __forceinline__ float2 h2f2(uint32_t h) {
    __half2 v = *(__half2*)&h;
    return __half22float2(v);
}
__device__ __forceinline__ uint32_t pack_e4m3(float x, float y, float z, float w) {
    uint16_t lo, hi;
    asm("cvt.rn.satfinite.e4m3x2.f32 %0, %1, %2;" : "=h"(lo) : "f"(y), "f"(x));
    asm("cvt.rn.satfinite.e4m3x2.f32 %0, %1, %2;" : "=h"(hi) : "f"(w), "f"(z));
    return (uint32_t)lo | ((uint32_t)hi << 16);
}

// ---------------------------------------------------------------------------
// Kernel 1: warp-per-row L2 normalize, write e4m3 z*2.4022, fp32 positives
// ---------------------------------------------------------------------------
__global__ void __launch_bounds__(256) norm_kernel(const float* __restrict__ emb_i,
                                                   const float* __restrict__ emb_j) {
    int lane = threadIdx.x & 31;
    int row = blockIdx.x * 8 + (threadIdx.x >> 5);
    const float4 a = ((const float4*)emb_i)[row * 32 + lane];
    const float4 b = ((const float4*)emb_j)[row * 32 + lane];
    float ssi = a.x * a.x + a.y * a.y + a.z * a.z + a.w * a.w;
    float ssj = b.x * b.x + b.y * b.y + b.z * b.z + b.w * b.w;
    float dot = a.x * b.x + a.y * b.y + a.z * b.z + a.w * b.w;
#pragma unroll
    for (int o = 16; o > 0; o >>= 1) {
        ssi += __shfl_xor_sync(0xffffffffu, ssi, o);
        ssj += __shfl_xor_sync(0xffffffffu, ssj, o);
        dot += __shfl_xor_sync(0xffffffffu, dot, o);
    }
    float inv_i = 1.0f / fmaxf(sqrtf(ssi), 1e-12f);
    float inv_j = 1.0f / fmaxf(sqrtf(ssj), 1e-12f);
    float si = inv_i * NORM_SCALE;
    float sj = inv_j * NORM_SCALE;

    g_zi_f8[row * 32 + lane] = pack_e4m3(a.x * si, a.y * si, a.z * si, a.w * si);
    g_zj_f8[row * 32 + lane] = pack_e4m3(b.x * sj, b.y * sj, b.z * sj, b.w * sj);
    if (lane == 0) {
        g_pos[row]    = dot * inv_i * inv_j;   // exact fp32 positive
        g_rowsum[row] = 0.0f;
        g_colsum[row] = 0.0f;
    }
}

// ---------------------------------------------------------------------------
// Kernel 2: persistent fp8 MMA (f16 accum), single-sync pipeline,
// packed-half2 epilogue with direct global atomics. 2 CTAs/SM, no spills.
// ---------------------------------------------------------------------------
__device__ __forceinline__ void prefetch_tile(int t, uint32_t dst, int tid) {
    int bx = t & 31, by = t >> 5;
    const char* srcA = (const char*)g_zi_f8 + (size_t)by * 128 * 128;
    const char* srcB = (const char*)g_zj_f8 + (size_t)bx * 128 * 128;
#pragma unroll
    for (int it = 0; it < 4; it++) {
        int i = it * 256 + tid;                 // [0,1024): row=i>>3, chunk=i&7
        uint32_t soff = (uint32_t)(i >> 3) * STRIDE + (uint32_t)(i & 7) * 16;
        cp16(dst + soff, srcA + (size_t)i * 16);
        cp16(dst + SM_TILE + soff, srcB + (size_t)i * 16);
    }
    asm volatile("cp.async.commit_group;" ::: "memory");
}

__global__ void __launch_bounds__(256, 2) sim_kernel() {
    extern __shared__ char smem[];
    uint32_t sbase = smem_u32(smem);
    int tid = threadIdx.x;
    int wid = tid >> 5;
    int l = tid & 31;
    int m_base = (wid & 1) * 64;
    int n_base = (wid >> 1) * 32;
    uint32_t lrow  = (uint32_t)(((l >> 3) & 1) * 8 + (l & 7));
    uint32_t lcolb = (uint32_t)((l >> 4) * 16);

    int t = blockIdx.x;
    if (t < NT) prefetch_tile(t, sbase, tid);     // prologue: buffer 0
    int buf = 0;

    for (; t < NT; t += GRID_SIM) {
        asm volatile("cp.async.wait_group 0;" ::: "memory");
        __syncthreads();      // cur tile resident; ALL warps done with buf^1 reads
        int tn = t + GRID_SIM;
        if (tn < NT)          // safe now: overlaps with compute below
            prefetch_tile(tn, sbase + (uint32_t)(buf ^ 1) * BUF_BYTES, tid);

        uint32_t cur = sbase + (uint32_t)buf * BUF_BYTES;
        uint32_t a_base = cur + (m_base + lrow) * STRIDE + lcolb;
        uint32_t b_base = cur + SM_TILE + (n_base + lrow) * STRIDE + lcolb;

        uint32_t c[4][4][2];                      // packed half2 accumulators
#pragma unroll
        for (int mf = 0; mf < 4; mf++)
#pragma unroll
            for (int nf = 0; nf < 4; nf++) { c[mf][nf][0] = 0u; c[mf][nf][1] = 0u; }

#pragma unroll
        for (int ks = 0; ks < 4; ks++) {          // K=128 fp8, 32 per MMA
            uint32_t koff = (uint32_t)ks * 32;
            uint32_t a0[4], a1[4], a2[4], a3[4];
#pragma unroll
            for (int mf = 0; mf < 4; mf++)
                ldm_x4(a0[mf], a1[mf], a2[mf], a3[mf],
                       a_base + (uint32_t)mf * 16 * STRIDE + koff);
            uint32_t bl0[2], bl1[2], bl2[2], bl3[2];
#pragma unroll
            for (int nh = 0; nh < 2; nh++)
                ldm_x4(bl0[nh], bl1[nh], bl2[nh], bl3[nh],
                       b_base + (uint32_t)nh * 16 * STRIDE + koff);
#pragma unroll
            for (int mf = 0; mf < 4; mf++) {
#pragma unroll
                for (int nh = 0; nh < 2; nh++) {
                    mma_fp8_h(c[mf][nh * 2][0], c[mf][nh * 2][1],
                              a0[mf], a1[mf], a2[mf], a3[mf], bl0[nh], bl2[nh]);
                    mma_fp8_h(c[mf][nh * 2 + 1][0], c[mf][nh * 2 + 1][1],
                              a0[mf], a1[mf], a2[mf], a3[mf], bl1[nh], bl3[nh]);
                }
            }
        }

        // --- epilogue: ex2.f16x2 + packed-half2 sums -> direct global REDG ---
        // c0 -> rows r @ (cc,cc+1); c1 -> rows r+8; r=l/4, cc=2(l%4)
        int rowBase = (t >> 5) * TILE;
        int colBase = (t & 31) * TILE;
        uint32_t hr0[4], hr1[4], cacc[4];
#pragma unroll
        for (int i = 0; i < 4; i++) { hr0[i] = 0u; hr1[i] = 0u; cacc[i] = 0u; }
#pragma unroll
        for (int mf = 0; mf < 4; mf++) {
#pragma unroll
            for (int nf = 0; nf < 4; nf++) {
                uint32_t e0 = ex2h2(c[mf][nf][0]);
                uint32_t e1 = ex2h2(c[mf][nf][1]);
                hr0[mf] = haddu(hr0[mf], e0);
                hr1[mf] = haddu(hr1[mf], e1);
                cacc[nf] = haddu(cacc[nf], haddu(e0, e1));
            }
        }
        // rows: packed shuffle over col-pair lanes (l&3), then REDG pair
#pragma unroll
        for (int mf = 0; mf < 4; mf++) {
            uint32_t a = hr0[mf], b = hr1[mf];
#pragma unroll
            for (int o = 1; o <= 2; o <<= 1) {
                a = haddu(a, __shfl_xor_sync(0xffffffffu, a, o));
                b = haddu(b, __shfl_xor_sync(0xffffffffu, b, o));
            }
            if ((l & 3) == 0) {
                float2 fa = h2f2(a), fb = h2f2(b);
                int r = rowBase + m_base + mf * 16 + (l >> 2);
                atomicAdd(&g_rowsum[r], fa.x + fa.y);
                atomicAdd(&g_rowsum[r + 8], fb.x + fb.y);
            }
        }
        // cols: packed shuffle over row lanes (l>>2), then REDG per component
#pragma unroll
        for (int nf = 0; nf < 4; nf++) {
            uint32_t a = cacc[nf];
#pragma unroll
            for (int o = 4; o <= 16; o <<= 1)
                a = haddu(a, __shfl_xor_sync(0xffffffffu, a, o));
            if (l < 4) {
                float2 fa = h2f2(a);
                int cc = colBase + n_base + nf * 8 + 2 * l;
                atomicAdd(&g_colsum[cc], fa.x);
                atomicAdd(&g_colsum[cc + 1], fa.y);
            }
        }
        buf ^= 1;
        // next iteration's wait+sync fences the buffer swap; atomics are
        // fire-and-forget (no-return REDG), ordering vs final_kernel is by
        // stream order of kernel launches.
    }
}

// ---------------------------------------------------------------------------
// Kernel 3: loss = ( sum log(rowsum)+log(colsum) - (2/T) sum pos ) / 2B
// ---------------------------------------------------------------------------
__global__ void final_kernel(float* __restrict__ out) {
    int t = threadIdx.x;
    double acc = 0.0;
    for (int i = t; i < NB; i += 256) {
        acc += (double)__logf(g_rowsum[i]) + (double)__logf(g_colsum[i])
             - 8.0 * (double)g_pos[i];                        // 2/T = 8
    }
    __shared__ double sd[256];
    sd[t] = acc;
    __syncthreads();
#pragma unroll
    for (int o = 128; o > 0; o >>= 1) {
        if (t < o) sd[t] += sd[t + o];
        __syncthreads();
    }
    if (t == 0) out[0] = (float)(sd[0] / (2.0 * NB));
}

extern "C" void kernel_launch(void* const* d_in, const int* in_sizes, int n_in,
                              void* d_out, int out_size) {
    const float* emb_i = (const float*)d_in[0];
    const float* emb_j = (const float*)d_in[1];
    float* out = (float*)d_out;

    cudaFuncSetAttribute(sim_kernel, cudaFuncAttributeMaxDynamicSharedMemorySize, SM_TOTAL);

    norm_kernel<<<NB / 8, 256>>>(emb_i, emb_j);
    sim_kernel<<<GRID_SIM, 256, SM_TOTAL>>>();
    final_kernel<<<1, 256>>>(out);
}

// round 16
// speedup vs baseline: 1.1319x; 1.0087x over previous
#include <cuda_runtime.h>
#include <cuda_fp16.h>
#include <math.h>
#include <cstdint>

#define NB 4096
#define ND 128
#define TILE 128
#define NT 1024                 // 32 x 32 tiles
#define GRID_SIM 296            // 2 CTAs per SM, persistent (no spills)
#define STRIDE 144              // smem bytes per 128-col fp8 row (128 + 16 pad)
#define SM_TILE (128 * STRIDE)  // 18432 B per tile
#define BUF_BYTES (2 * SM_TILE) // A + B = 36864 B
#define SM_TOTAL (2 * BUF_BYTES)// double buffered = 73728 B
// z scaled by sqrt(4*log2(e)) = 2.4022448 -> accumulator = sim * 4*log2(e),
// so exp(sim/T) = ex2(accumulator) directly.
#define NORM_SCALE 2.4022448f

// ---------------- scratch (no allocations allowed) ----------------
__device__ __align__(16) uint32_t g_zi_f8[NB * 32];  // e4m3 z_i*2.4022
__device__ __align__(16) uint32_t g_zj_f8[NB * 32];  // e4m3 z_j*2.4022
__device__ float g_rowsum[NB];
__device__ float g_colsum[NB];
__device__ float g_pos[NB];
__device__ int g_done;          // last-CTA completion counter

__device__ __forceinline__ uint32_t smem_u32(const void* p) {
    uint32_t a;
    asm("{ .reg .u64 t; cvta.to.shared.u64 t, %1; cvt.u32.u64 %0, t; }" : "=r"(a) : "l"(p));
    return a;
}
__device__ __forceinline__ void cp16(uint32_t dst, const void* src) {
    asm volatile("cp.async.cg.shared.global [%0], [%1], 16;" :: "r"(dst), "l"(src));
}
__device__ __forceinline__ void ldm_x4(uint32_t& r0, uint32_t& r1, uint32_t& r2,
                                       uint32_t& r3, uint32_t addr) {
    asm volatile("ldmatrix.sync.aligned.m8n8.x4.shared.b16 {%0,%1,%2,%3}, [%4];"
                 : "=r"(r0), "=r"(r1), "=r"(r2), "=r"(r3) : "r"(addr));
}
__device__ __forceinline__ void mma_fp8_h(uint32_t& c0, uint32_t& c1,
                                          uint32_t a0, uint32_t a1, uint32_t a2, uint32_t a3,
                                          uint32_t b0, uint32_t b1) {
    asm volatile("mma.sync.aligned.m16n8k32.row.col.f16.e4m3.e4m3.f16 "
                 "{%0,%1}, {%2,%3,%4,%5}, {%6,%7}, {%0,%1};"
                 : "+r"(c0), "+r"(c1)
                 : "r"(a0), "r"(a1), "r"(a2), "r"(a3), "r"(b0), "r"(b1));
}
__device__ __forceinline__ uint32_t ex2h2(uint32_t x) {
    uint32_t r;
    asm("ex2.approx.f16x2 %0, %1;" : "=r"(r) : "r"(x));
    return r;
}
__device__ __forceinline__ uint32_t haddu(uint32_t a, uint32_t b) {
    uint32_t r;
    asm("add.rn.f16x2 %0, %1, %2;" : "=r"(r) : "r"(a), "r"(b));
    return r;
}
__device__ __forceinline__ float2 h2f2(uint32_t h) {
    __half2 v = *(__half2*)&h;
    return __half22float2(v);
}
__device__ __forceinline__ uint32_t pack_e4m3(float x, float y, float z, float w) {
    uint16_t lo, hi;
    asm("cvt.rn.satfinite.e4m3x2.f32 %0, %1, %2;" : "=h"(lo) : "f"(y), "f"(x));
    asm("cvt.rn.satfinite.e4m3x2.f32 %0, %1, %2;" : "=h"(hi) : "f"(w), "f"(z));
    return (uint32_t)lo | ((uint32_t)hi << 16);
}

// ---------------------------------------------------------------------------
// Kernel 1: warp-per-row L2 normalize, write e4m3 z*2.4022, fp32 positives
// ---------------------------------------------------------------------------
__global__ void __launch_bounds__(256) norm_kernel(const float* __restrict__ emb_i,
                                                   const float* __restrict__ emb_j) {
    int lane = threadIdx.x & 31;
    int row = blockIdx.x * 8 + (threadIdx.x >> 5);
    const float4 a = ((const float4*)emb_i)[row * 32 + lane];
    const float4 b = ((const float4*)emb_j)[row * 32 + lane];
    float ssi = a.x * a.x + a.y * a.y + a.z * a.z + a.w * a.w;
    float ssj = b.x * b.x + b.y * b.y + b.z * b.z + b.w * b.w;
    float dot = a.x * b.x + a.y * b.y + a.z * b.z + a.w * b.w;
#pragma unroll
    for (int o = 16; o > 0; o >>= 1) {
        ssi += __shfl_xor_sync(0xffffffffu, ssi, o);
        ssj += __shfl_xor_sync(0xffffffffu, ssj, o);
        dot += __shfl_xor_sync(0xffffffffu, dot, o);
    }
    float inv_i = 1.0f / fmaxf(sqrtf(ssi), 1e-12f);
    float inv_j = 1.0f / fmaxf(sqrtf(ssj), 1e-12f);
    float si = inv_i * NORM_SCALE;
    float sj = inv_j * NORM_SCALE;

    g_zi_f8[row * 32 + lane] = pack_e4m3(a.x * si, a.y * si, a.z * si, a.w * si);
    g_zj_f8[row * 32 + lane] = pack_e4m3(b.x * sj, b.y * sj, b.z * sj, b.w * sj);
    if (lane == 0) {
        g_pos[row]    = dot * inv_i * inv_j;   // exact fp32 positive
        g_rowsum[row] = 0.0f;
        g_colsum[row] = 0.0f;
    }
}

// ---------------------------------------------------------------------------
// Kernel 2: persistent fp8 MMA (f16 accum), ldsm software pipeline (ks+1
// fragments prefetched), REDG epilogue, fused last-CTA final reduce.
// ---------------------------------------------------------------------------
__device__ __forceinline__ void prefetch_tile(int t, uint32_t dst, int tid) {
    int bx = t & 31, by = t >> 5;
    const char* srcA = (const char*)g_zi_f8 + (size_t)by * 128 * 128;
    const char* srcB = (const char*)g_zj_f8 + (size_t)bx * 128 * 128;
#pragma unroll
    for (int it = 0; it < 4; it++) {
        int i = it * 256 + tid;                 // [0,1024): row=i>>3, chunk=i&7
        uint32_t soff = (uint32_t)(i >> 3) * STRIDE + (uint32_t)(i & 7) * 16;
        cp16(dst + soff, srcA + (size_t)i * 16);
        cp16(dst + SM_TILE + soff, srcB + (size_t)i * 16);
    }
    asm volatile("cp.async.commit_group;" ::: "memory");
}

__global__ void __launch_bounds__(256, 2) sim_kernel(float* __restrict__ out) {
    extern __shared__ char smem[];
    uint32_t sbase = smem_u32(smem);
    int tid = threadIdx.x;
    int wid = tid >> 5;
    int l = tid & 31;
    int m_base = (wid & 1) * 64;
    int n_base = (wid >> 1) * 32;
    uint32_t lrow  = (uint32_t)(((l >> 3) & 1) * 8 + (l & 7));
    uint32_t lcolb = (uint32_t)((l >> 4) * 16);

    int t = blockIdx.x;
    if (t < NT) prefetch_tile(t, sbase, tid);     // prologue: buffer 0
    int buf = 0;

    for (; t < NT; t += GRID_SIM) {
        asm volatile("cp.async.wait_group 0;" ::: "memory");
        __syncthreads();      // cur tile resident; ALL warps done with buf^1 reads
        int tn = t + GRID_SIM;
        if (tn < NT)          // safe now: overlaps with compute below
            prefetch_tile(tn, sbase + (uint32_t)(buf ^ 1) * BUF_BYTES, tid);

        uint32_t cur = sbase + (uint32_t)buf * BUF_BYTES;
        uint32_t a_base = cur + (m_base + lrow) * STRIDE + lcolb;
        uint32_t b_base = cur + SM_TILE + (n_base + lrow) * STRIDE + lcolb;

        uint32_t c[4][4][2];                      // packed half2 accumulators
#pragma unroll
        for (int mf = 0; mf < 4; mf++)
#pragma unroll
            for (int nf = 0; nf < 4; nf++) { c[mf][nf][0] = 0u; c[mf][nf][1] = 0u; }

        // --- ldsm software pipeline: fragments for ks+1 loaded before ks MMA ---
        uint32_t a0[2][4], a1[2][4], a2[2][4], a3[2][4];
        uint32_t bl0[2][2], bl1[2][2], bl2[2][2], bl3[2][2];
#pragma unroll
        for (int mf = 0; mf < 4; mf++)
            ldm_x4(a0[0][mf], a1[0][mf], a2[0][mf], a3[0][mf],
                   a_base + (uint32_t)mf * 16 * STRIDE);
#pragma unroll
        for (int nh = 0; nh < 2; nh++)
            ldm_x4(bl0[0][nh], bl1[0][nh], bl2[0][nh], bl3[0][nh],
                   b_base + (uint32_t)nh * 16 * STRIDE);

#pragma unroll
        for (int ks = 0; ks < 4; ks++) {          // K=128 fp8, 32 per MMA
            int cb = ks & 1;
            if (ks < 3) {
                uint32_t koff = (uint32_t)(ks + 1) * 32;
#pragma unroll
                for (int mf = 0; mf < 4; mf++)
                    ldm_x4(a0[cb ^ 1][mf], a1[cb ^ 1][mf],
                           a2[cb ^ 1][mf], a3[cb ^ 1][mf],
                           a_base + (uint32_t)mf * 16 * STRIDE + koff);
#pragma unroll
                for (int nh = 0; nh < 2; nh++)
                    ldm_x4(bl0[cb ^ 1][nh], bl1[cb ^ 1][nh],
                           bl2[cb ^ 1][nh], bl3[cb ^ 1][nh],
                           b_base + (uint32_t)nh * 16 * STRIDE + koff);
            }
#pragma unroll
            for (int mf = 0; mf < 4; mf++) {
#pragma unroll
                for (int nh = 0; nh < 2; nh++) {
                    mma_fp8_h(c[mf][nh * 2][0], c[mf][nh * 2][1],
                              a0[cb][mf], a1[cb][mf], a2[cb][mf], a3[cb][mf],
                              bl0[cb][nh], bl2[cb][nh]);
                    mma_fp8_h(c[mf][nh * 2 + 1][0], c[mf][nh * 2 + 1][1],
                              a0[cb][mf], a1[cb][mf], a2[cb][mf], a3[cb][mf],
                              bl1[cb][nh], bl3[cb][nh]);
                }
            }
        }

        // --- epilogue: ex2.f16x2 + packed-half2 sums -> direct global REDG ---
        // c0 -> rows r @ (cc,cc+1); c1 -> rows r+8; r=l/4, cc=2(l%4)
        int rowBase = (t >> 5) * TILE;
        int colBase = (t & 31) * TILE;
        uint32_t hr0[4], hr1[4], cacc[4];
#pragma unroll
        for (int i = 0; i < 4; i++) { hr0[i] = 0u; hr1[i] = 0u; cacc[i] = 0u; }
#pragma unroll
        for (int mf = 0; mf < 4; mf++) {
#pragma unroll
            for (int nf = 0; nf < 4; nf++) {
                uint32_t e0 = ex2h2(c[mf][nf][0]);
                uint32_t e1 = ex2h2(c[mf][nf][1]);
                hr0[mf] = haddu(hr0[mf], e0);
                hr1[mf] = haddu(hr1[mf], e1);
                cacc[nf] = haddu(cacc[nf], haddu(e0, e1));
            }
        }
        // rows: packed shuffle over col-pair lanes (l&3), then REDG pair
#pragma unroll
        for (int mf = 0; mf < 4; mf++) {
            uint32_t a = hr0[mf], b = hr1[mf];
#pragma unroll
            for (int o = 1; o <= 2; o <<= 1) {
                a = haddu(a, __shfl_xor_sync(0xffffffffu, a, o));
                b = haddu(b, __shfl_xor_sync(0xffffffffu, b, o));
            }
            if ((l & 3) == 0) {
                float2 fa = h2f2(a), fb = h2f2(b);
                int r = rowBase + m_base + mf * 16 + (l >> 2);
                atomicAdd(&g_rowsum[r], fa.x + fa.y);
                atomicAdd(&g_rowsum[r + 8], fb.x + fb.y);
            }
        }
        // cols: packed shuffle over row lanes (l>>2), then REDG per component
#pragma unroll
        for (int nf = 0; nf < 4; nf++) {
            uint32_t a = cacc[nf];
#pragma unroll
            for (int o = 4; o <= 16; o <<= 1)
                a = haddu(a, __shfl_xor_sync(0xffffffffu, a, o));
            if (l < 4) {
                float2 fa = h2f2(a);
                int cc = colBase + n_base + nf * 8 + 2 * l;
                atomicAdd(&g_colsum[cc], fa.x);
                atomicAdd(&g_colsum[cc + 1], fa.y);
            }
        }
        buf ^= 1;
    }

    // ---------- fused final: last CTA to finish reduces the loss ----------
    __shared__ int s_rank;
    __shared__ double sd[256];
    __threadfence();          // make this CTA's REDGs globally visible
    __syncthreads();
    if (tid == 0) s_rank = atomicAdd(&g_done, 1);
    __syncthreads();
    if (s_rank == GRID_SIM - 1) {
        __threadfence();      // acquire: all other CTAs' sums visible
        double acc = 0.0;
        for (int i = tid; i < NB; i += 256) {
            acc += (double)__logf(g_rowsum[i]) + (double)__logf(g_colsum[i])
                 - 8.0 * (double)g_pos[i];        // 2/T = 8
        }
        sd[tid] = acc;
        __syncthreads();
#pragma unroll
        for (int o = 128; o > 0; o >>= 1) {
            if (tid < o) sd[tid] += sd[tid + o];
            __syncthreads();
        }
        if (tid == 0) {
            out[0] = (float)(sd[0] / (2.0 * NB));
            g_done = 0;       // reset for next graph replay
        }
    }
}

extern "C" void kernel_launch(void* const* d_in, const int* in_sizes, int n_in,
                              void* d_out, int out_size) {
    const float* emb_i = (const float*)d_in[0];
    const float* emb_j = (const float*)d_in[1];
    float* out = (float*)d_out;

    cudaFuncSetAttribute(sim_kernel, cudaFuncAttributeMaxDynamicSharedMemorySize, SM_TOTAL);

    norm_kernel<<<NB / 8, 256>>>(emb_i, emb_j);
    sim_kernel<<<GRID_SIM, 256, SM_TOTAL>>>(out);
}